// round 9
// baseline (speedup 1.0000x reference)
#include <cuda_runtime.h>

#define NN 200000
#define DD 64
#define EE 600000
#define TE 1200000           // 2*EE directed edges after symmetrization
#define NBLK 196             // ceil(NN / 1024) build blocks

// Scratch: __device__ globals (no allocation allowed anywhere).
__device__ float g_xn[(size_t)NN * DD];    // l2-normalized x
__device__ float g_x1[(size_t)NN * DD];    // layer-1 output
__device__ int   g_cnt[NN];                // in-degree
__device__ int   g_off[NN];                // CSR bucket start
__device__ int   g_cur[NN];                // fill cursors
__device__ int   g_total;                  // global bucket cursor
__device__ int2  g_csr[TE];                // CSR slot: {src, __float_as_int(w)}

// ---------------------------------------------------------------------------
// Degree histogram: one thread per directed edge.
// Edge e: src = ei[e]; dst = ei[e+EE] for e<EE, ei[e-EE] for e>=EE.
__global__ void k_count(const int* __restrict__ ei) {
    int e = blockIdx.x * blockDim.x + threadIdx.x;
    if (e >= TE) return;
    int dst = (e < EE) ? ei[e + EE] : ei[e - EE];
    if ((unsigned)dst < (unsigned)NN) atomicAdd(&g_cnt[dst], 1);
}

// ---------------------------------------------------------------------------
// Bucket allocation: each block scans 1024 counts, grabs a contiguous range
// from g_total with ONE atomic, writes off/cur. Bucket placement order across
// blocks is nondeterministic but irrelevant (content per bucket is fixed).
__global__ void k_build_off() {
    __shared__ int sh[256];
    __shared__ int base_sh;
    int t = threadIdx.x;
    int b = blockIdx.x * 1024 + t * 4;
    int v0 = (b + 0 < NN) ? g_cnt[b + 0] : 0;
    int v1 = (b + 1 < NN) ? g_cnt[b + 1] : 0;
    int v2 = (b + 2 < NN) ? g_cnt[b + 2] : 0;
    int v3 = (b + 3 < NN) ? g_cnt[b + 3] : 0;
    int s = v0 + v1 + v2 + v3;
    sh[t] = s;
    __syncthreads();
    #pragma unroll
    for (int o = 1; o < 256; o <<= 1) {
        int x = (t >= o) ? sh[t - o] : 0;
        __syncthreads();
        sh[t] += x;
        __syncthreads();
    }
    if (t == 255) base_sh = atomicAdd(&g_total, sh[255]);
    __syncthreads();
    int excl = base_sh + sh[t] - s;
    if (b + 0 < NN) { g_off[b + 0] = excl;                g_cur[b + 0] = excl; }
    if (b + 1 < NN) { g_off[b + 1] = excl + v0;           g_cur[b + 1] = excl + v0; }
    if (b + 2 < NN) { g_off[b + 2] = excl + v0 + v1;      g_cur[b + 2] = excl + v0 + v1; }
    if (b + 3 < NN) { g_off[b + 3] = excl + v0 + v1 + v2; g_cur[b + 3] = excl + v0 + v1 + v2; }
}

// ---------------------------------------------------------------------------
// CSR fill: place {src, w} pair into dst's bucket (one STG.64).
__global__ void k_fill(const int* __restrict__ ei, const float* __restrict__ w) {
    int e = blockIdx.x * blockDim.x + threadIdx.x;
    if (e >= TE) return;
    int src = ei[e];
    int dst = (e < EE) ? ei[e + EE] : ei[e - EE];
    if ((unsigned)src >= (unsigned)NN || (unsigned)dst >= (unsigned)NN) return;
    int pos = atomicAdd(&g_cur[dst], 1);
    g_csr[pos] = make_int2(src, __float_as_int(w[e]));
}

// ---------------------------------------------------------------------------
// Row-wise L2 normalize: one warp covers 2 rows; each half-warp (16 lanes)
// does one row with float4 per lane (16*16B = 256B = full row).
__global__ void k_norm(const float* __restrict__ x) {
    int warp = threadIdx.x >> 5;
    int lane = threadIdx.x & 31;
    int h    = lane >> 4;          // which row within the warp's pair
    int f    = lane & 15;          // feature group
    int row  = blockIdx.x * 16 + warp * 2 + h;
    if (row >= NN) return;
    const float4 v = *(const float4*)(x + (size_t)row * DD + f * 4);
    float s = v.x * v.x + v.y * v.y + v.z * v.z + v.w * v.w;
    #pragma unroll
    for (int o = 8; o; o >>= 1) s += __shfl_xor_sync(0xffffffffu, s, o);
    float inv = 1.0f / fmaxf(sqrtf(s), 1e-12f);
    *(float4*)(g_xn + (size_t)row * DD + f * 4) =
        make_float4(v.x * inv, v.y * inv, v.z * inv, v.w * inv);
}

// ---------------------------------------------------------------------------
// Pull conv (R2 structure + MANUAL 4-wide unroll): one warp per dst row,
// float2 per lane. Coalesced 32-edge batch preload of {src,w} into registers;
// inner loop broadcasts 4 edges at a time and issues 4 explicitly independent
// LDG.64s back-to-back (MLP=4 on the L2 latency chain), scalar tail for m%4.
// Atomic-free; fused epilogue.
template <bool FINAL>
__global__ void k_gather(const float* __restrict__ xin, float* __restrict__ xout) {
    int row  = blockIdx.x * 8 + (threadIdx.x >> 5);
    if (row >= NN) return;
    int lane = threadIdx.x & 31;
    int start = __ldg(&g_off[row]);
    int cnt   = __ldg(&g_cnt[row]);
    const float* xl = xin + lane * 2;
    float2 acc = make_float2(0.f, 0.f);
    for (int b = 0; b < cnt; b += 32) {
        int idx = b + lane;
        int2 pr = (idx < cnt) ? __ldg(&g_csr[start + idx]) : make_int2(0, 0);
        int m = min(32, cnt - b);
        int j = 0;
        for (; j + 4 <= m; j += 4) {
            int s0 = __shfl_sync(0xffffffffu, pr.x, j + 0);
            int s1 = __shfl_sync(0xffffffffu, pr.x, j + 1);
            int s2 = __shfl_sync(0xffffffffu, pr.x, j + 2);
            int s3 = __shfl_sync(0xffffffffu, pr.x, j + 3);
            float w0 = __int_as_float(__shfl_sync(0xffffffffu, pr.y, j + 0));
            float w1 = __int_as_float(__shfl_sync(0xffffffffu, pr.y, j + 1));
            float w2 = __int_as_float(__shfl_sync(0xffffffffu, pr.y, j + 2));
            float w3 = __int_as_float(__shfl_sync(0xffffffffu, pr.y, j + 3));
            float2 v0 = *(const float2*)(xl + (size_t)s0 * DD);
            float2 v1 = *(const float2*)(xl + (size_t)s1 * DD);
            float2 v2 = *(const float2*)(xl + (size_t)s2 * DD);
            float2 v3 = *(const float2*)(xl + (size_t)s3 * DD);
            acc.x += w0 * v0.x; acc.y += w0 * v0.y;
            acc.x += w1 * v1.x; acc.y += w1 * v1.y;
            acc.x += w2 * v2.x; acc.y += w2 * v2.y;
            acc.x += w3 * v3.x; acc.y += w3 * v3.y;
        }
        for (; j < m; j++) {
            int   sj = __shfl_sync(0xffffffffu, pr.x, j);
            float wj = __int_as_float(__shfl_sync(0xffffffffu, pr.y, j));
            float2 v = *(const float2*)(xl + (size_t)sj * DD);
            acc.x += wj * v.x;
            acc.y += wj * v.y;
        }
    }
    float sc = 1.0f / fmaxf((float)cnt, 1.0f);
    acc.x *= sc; acc.y *= sc;
    acc.x = acc.x >= 0.f ? acc.x : 0.01f * acc.x;
    acc.y = acc.y >= 0.f ? acc.y : 0.01f * acc.y;
    size_t o = (size_t)row * DD + lane * 2;
    if (FINAL) {
        float2 xn = *(const float2*)(g_xn + o);
        float2 x1 = *(const float2*)(g_x1 + o);
        acc.x += xn.x + x1.x;
        acc.y += xn.y + x1.y;
    }
    *(float2*)(xout + o) = acc;
}

// ---------------------------------------------------------------------------
extern "C" void kernel_launch(void* const* d_in, const int* in_sizes, int n_in,
                              void* d_out, int out_size) {
    const float* emb = (const float*)d_in[0];   // [NN, DD] float32
    const int*   ei  = (const int*)d_in[1];     // [2, EE] int32
    const float* w   = (const float*)d_in[2];   // [TE, 1] float32
    float* out = (float*)d_out;

    void *p_cnt, *p_tot, *p_xn, *p_x1;
    cudaGetSymbolAddress(&p_cnt, g_cnt);
    cudaGetSymbolAddress(&p_tot, g_total);
    cudaGetSymbolAddress(&p_xn,  g_xn);
    cudaGetSymbolAddress(&p_x1,  g_x1);

    const int THR = 256;

    // CSR build: degrees -> bucket alloc -> fill
    cudaMemsetAsync(p_cnt, 0, NN * sizeof(int));
    cudaMemsetAsync(p_tot, 0, sizeof(int));
    k_count<<<(TE + THR - 1) / THR, THR>>>(ei);
    k_build_off<<<NBLK, THR>>>();
    k_fill<<<(TE + THR - 1) / THR, THR>>>(ei, w);

    // x = l2norm(emb)
    k_norm<<<(NN + 15) / 16, THR>>>(emb);

    // layer 1: x1 = leaky(gather(xn)/deg)            (fused epilogue)
    k_gather<false><<<(NN + 7) / 8, THR>>>((const float*)p_xn, (float*)p_x1);
    // layer 2: out = xn + x1 + leaky(gather(x1)/deg) (fused epilogue)
    k_gather<true><<<(NN + 7) / 8, THR>>>((const float*)p_x1, out);
}

// round 10
// speedup vs baseline: 1.1784x; 1.1784x over previous
#include <cuda_runtime.h>

#define NN 200000
#define DD 64
#define EE 600000
#define TE 1200000           // 2*EE directed edges after symmetrization
#define NBLK 196             // ceil(NN / 1024) build blocks

// Scratch: __device__ globals (no allocation allowed anywhere).
__device__ float g_xn[(size_t)NN * DD];    // l2-normalized x
__device__ float g_x1[(size_t)NN * DD];    // layer-1 output
__device__ int   g_cnt[NN];                // in-degree
__device__ int   g_off[NN];                // CSR bucket start
__device__ int   g_cur[NN];                // fill cursors
__device__ int   g_total;                  // global bucket cursor
__device__ int2  g_csr[TE];                // CSR slot: {src, __float_as_int(w)}

// ---------------------------------------------------------------------------
// Degree histogram: one thread per directed edge.
// Edge e: src = ei[e]; dst = ei[e+EE] for e<EE, ei[e-EE] for e>=EE.
__global__ void k_count(const int* __restrict__ ei) {
    int e = blockIdx.x * blockDim.x + threadIdx.x;
    if (e >= TE) return;
    int dst = (e < EE) ? ei[e + EE] : ei[e - EE];
    if ((unsigned)dst < (unsigned)NN) atomicAdd(&g_cnt[dst], 1);
}

// ---------------------------------------------------------------------------
// Bucket allocation: each block scans 1024 counts, grabs a contiguous range
// from g_total with ONE atomic, writes off/cur. Bucket placement order across
// blocks is nondeterministic but irrelevant (content per bucket is fixed).
__global__ void k_build_off() {
    __shared__ int sh[256];
    __shared__ int base_sh;
    int t = threadIdx.x;
    int b = blockIdx.x * 1024 + t * 4;
    int v0 = (b + 0 < NN) ? g_cnt[b + 0] : 0;
    int v1 = (b + 1 < NN) ? g_cnt[b + 1] : 0;
    int v2 = (b + 2 < NN) ? g_cnt[b + 2] : 0;
    int v3 = (b + 3 < NN) ? g_cnt[b + 3] : 0;
    int s = v0 + v1 + v2 + v3;
    sh[t] = s;
    __syncthreads();
    #pragma unroll
    for (int o = 1; o < 256; o <<= 1) {
        int x = (t >= o) ? sh[t - o] : 0;
        __syncthreads();
        sh[t] += x;
        __syncthreads();
    }
    if (t == 255) base_sh = atomicAdd(&g_total, sh[255]);
    __syncthreads();
    int excl = base_sh + sh[t] - s;
    if (b + 0 < NN) { g_off[b + 0] = excl;                g_cur[b + 0] = excl; }
    if (b + 1 < NN) { g_off[b + 1] = excl + v0;           g_cur[b + 1] = excl + v0; }
    if (b + 2 < NN) { g_off[b + 2] = excl + v0 + v1;      g_cur[b + 2] = excl + v0 + v1; }
    if (b + 3 < NN) { g_off[b + 3] = excl + v0 + v1 + v2; g_cur[b + 3] = excl + v0 + v1 + v2; }
}

// ---------------------------------------------------------------------------
// CSR fill: place {src, w} pair into dst's bucket (one STG.64).
__global__ void k_fill(const int* __restrict__ ei, const float* __restrict__ w) {
    int e = blockIdx.x * blockDim.x + threadIdx.x;
    if (e >= TE) return;
    int src = ei[e];
    int dst = (e < EE) ? ei[e + EE] : ei[e - EE];
    if ((unsigned)src >= (unsigned)NN || (unsigned)dst >= (unsigned)NN) return;
    int pos = atomicAdd(&g_cur[dst], 1);
    g_csr[pos] = make_int2(src, __float_as_int(w[e]));
}

// ---------------------------------------------------------------------------
// Row-wise L2 normalize: one warp covers 2 rows; each half-warp (16 lanes)
// does one row with float4 per lane (16*16B = 256B = full row).
__global__ void k_norm(const float* __restrict__ x) {
    int warp = threadIdx.x >> 5;
    int lane = threadIdx.x & 31;
    int h    = lane >> 4;          // which row within the warp's pair
    int f    = lane & 15;          // feature group
    int row  = blockIdx.x * 16 + warp * 2 + h;
    if (row >= NN) return;
    const float4 v = *(const float4*)(x + (size_t)row * DD + f * 4);
    float s = v.x * v.x + v.y * v.y + v.z * v.z + v.w * v.w;
    #pragma unroll
    for (int o = 8; o; o >>= 1) s += __shfl_xor_sync(0xffffffffu, s, o);
    float inv = 1.0f / fmaxf(sqrtf(s), 1e-12f);
    *(float4*)(g_xn + (size_t)row * DD + f * 4) =
        make_float4(v.x * inv, v.y * inv, v.z * inv, v.w * inv);
}

// ---------------------------------------------------------------------------
// Pull conv — EXACT R2 structure (best measured): one warp per dst row,
// float2 per lane. Coalesced 32-edge batch preload of {src,w}; simple ROLLED
// shfl-broadcast inner loop, one LDG per iteration. Evidence (R7/R9): any
// load front-batching deepens the cross-CTA L1tex queue at occ~8 and
// regresses; TLP already covers L2 latency. Atomic-free; fused epilogue.
template <bool FINAL>
__global__ void k_gather(const float* __restrict__ xin, float* __restrict__ xout) {
    int row  = blockIdx.x * 8 + (threadIdx.x >> 5);
    if (row >= NN) return;
    int lane = threadIdx.x & 31;
    int start = __ldg(&g_off[row]);
    int cnt   = __ldg(&g_cnt[row]);
    float2 acc = make_float2(0.f, 0.f);
    for (int b = 0; b < cnt; b += 32) {
        int idx = b + lane;
        int2 pr = (idx < cnt) ? __ldg(&g_csr[start + idx]) : make_int2(0, 0);
        int m = min(32, cnt - b);
        for (int j = 0; j < m; j++) {
            int   sj = __shfl_sync(0xffffffffu, pr.x, j);
            float wj = __int_as_float(__shfl_sync(0xffffffffu, pr.y, j));
            const float2 v = *(const float2*)(xin + (size_t)sj * DD + lane * 2);
            acc.x += wj * v.x;
            acc.y += wj * v.y;
        }
    }
    float sc = 1.0f / fmaxf((float)cnt, 1.0f);
    acc.x *= sc; acc.y *= sc;
    acc.x = acc.x >= 0.f ? acc.x : 0.01f * acc.x;
    acc.y = acc.y >= 0.f ? acc.y : 0.01f * acc.y;
    size_t o = (size_t)row * DD + lane * 2;
    if (FINAL) {
        float2 xn = *(const float2*)(g_xn + o);
        float2 x1 = *(const float2*)(g_x1 + o);
        acc.x += xn.x + x1.x;
        acc.y += xn.y + x1.y;
    }
    *(float2*)(xout + o) = acc;
}

// ---------------------------------------------------------------------------
extern "C" void kernel_launch(void* const* d_in, const int* in_sizes, int n_in,
                              void* d_out, int out_size) {
    const float* emb = (const float*)d_in[0];   // [NN, DD] float32
    const int*   ei  = (const int*)d_in[1];     // [2, EE] int32
    const float* w   = (const float*)d_in[2];   // [TE, 1] float32
    float* out = (float*)d_out;

    void *p_cnt, *p_tot, *p_xn, *p_x1;
    cudaGetSymbolAddress(&p_cnt, g_cnt);
    cudaGetSymbolAddress(&p_tot, g_total);
    cudaGetSymbolAddress(&p_xn,  g_xn);
    cudaGetSymbolAddress(&p_x1,  g_x1);

    const int THR = 256;

    // CSR build: degrees -> bucket alloc -> fill
    cudaMemsetAsync(p_cnt, 0, NN * sizeof(int));
    cudaMemsetAsync(p_tot, 0, sizeof(int));
    k_count<<<(TE + THR - 1) / THR, THR>>>(ei);
    k_build_off<<<NBLK, THR>>>();
    k_fill<<<(TE + THR - 1) / THR, THR>>>(ei, w);

    // x = l2norm(emb)
    k_norm<<<(NN + 15) / 16, THR>>>(emb);

    // layer 1: x1 = leaky(gather(xn)/deg)            (fused epilogue)
    k_gather<false><<<(NN + 7) / 8, THR>>>((const float*)p_xn, (float*)p_x1);
    // layer 2: out = xn + x1 + leaky(gather(x1)/deg) (fused epilogue)
    k_gather<true><<<(NN + 7) / 8, THR>>>((const float*)p_x1, out);
}

// round 13
// speedup vs baseline: 1.1887x; 1.0088x over previous
#include <cuda_runtime.h>

#define NN 200000
#define DD 64
#define EE 600000
#define TE 1200000           // 2*EE directed edges after symmetrization
#define NBLK 196             // ceil(NN / 1024) build blocks

// Scratch: __device__ globals (no allocation allowed anywhere).
__device__ float g_x1[(size_t)NN * DD];    // layer-1 output
__device__ float g_rn[NN];                 // 1 / max(||emb_row||, eps)
__device__ int   g_cnt[NN + 1];            // in-degree; [NN] = global cursor
__device__ int   g_off[NN];                // CSR bucket start
__device__ int   g_cur[NN];                // fill cursors
__device__ int2  g_csr1[TE];               // layer-1 slot: {src, bits(w*rn[src])}
__device__ int2  g_csr2[TE];               // layer-2 slot: {src, bits(w)}

// ---------------------------------------------------------------------------
// Per-row inverse L2 norm: one warp covers 2 rows; each half-warp (16 lanes)
// reads one row as float4 (256B); f==0 lane writes rn. No xn materialization.
__global__ void k_rnorm(const float* __restrict__ x) {
    int warp = threadIdx.x >> 5;
    int lane = threadIdx.x & 31;
    int h    = lane >> 4;
    int f    = lane & 15;
    int row  = blockIdx.x * 16 + warp * 2 + h;
    if (row >= NN) return;
    const float4 v = *(const float4*)(x + (size_t)row * DD + f * 4);
    float s = v.x * v.x + v.y * v.y + v.z * v.z + v.w * v.w;
    #pragma unroll
    for (int o = 8; o; o >>= 1) s += __shfl_xor_sync(0xffffffffu, s, o);
    if (f == 0) g_rn[row] = 1.0f / fmaxf(sqrtf(s), 1e-12f);
}

// ---------------------------------------------------------------------------
// Degree histogram: one thread per directed edge.
// Edge e: src = ei[e]; dst = ei[e+EE] for e<EE, ei[e-EE] for e>=EE.
__global__ void k_count(const int* __restrict__ ei) {
    int e = blockIdx.x * blockDim.x + threadIdx.x;
    if (e >= TE) return;
    int dst = (e < EE) ? ei[e + EE] : ei[e - EE];
    if ((unsigned)dst < (unsigned)NN) atomicAdd(&g_cnt[dst], 1);
}

// ---------------------------------------------------------------------------
// Bucket allocation: each block scans 1024 counts, grabs a contiguous range
// from the global cursor (g_cnt[NN]) with ONE atomic, writes off/cur. Bucket
// placement order is nondeterministic but content per bucket is fixed.
__global__ void k_build_off() {
    __shared__ int sh[256];
    __shared__ int base_sh;
    int t = threadIdx.x;
    int b = blockIdx.x * 1024 + t * 4;
    int v0 = (b + 0 < NN) ? g_cnt[b + 0] : 0;
    int v1 = (b + 1 < NN) ? g_cnt[b + 1] : 0;
    int v2 = (b + 2 < NN) ? g_cnt[b + 2] : 0;
    int v3 = (b + 3 < NN) ? g_cnt[b + 3] : 0;
    int s = v0 + v1 + v2 + v3;
    sh[t] = s;
    __syncthreads();
    #pragma unroll
    for (int o = 1; o < 256; o <<= 1) {
        int x = (t >= o) ? sh[t - o] : 0;
        __syncthreads();
        sh[t] += x;
        __syncthreads();
    }
    if (t == 255) base_sh = atomicAdd(&g_cnt[NN], sh[255]);
    __syncthreads();
    int excl = base_sh + sh[t] - s;
    if (b + 0 < NN) { g_off[b + 0] = excl;                g_cur[b + 0] = excl; }
    if (b + 1 < NN) { g_off[b + 1] = excl + v0;           g_cur[b + 1] = excl + v0; }
    if (b + 2 < NN) { g_off[b + 2] = excl + v0 + v1;      g_cur[b + 2] = excl + v0 + v1; }
    if (b + 3 < NN) { g_off[b + 3] = excl + v0 + v1 + v2; g_cur[b + 3] = excl + v0 + v1 + v2; }
}

// ---------------------------------------------------------------------------
// CSR fill: layer-1 slot carries w*rn[src] (folds l2-normalize into the edge
// weight); layer-2 slot carries plain w. Two STG.64 per edge.
__global__ void k_fill(const int* __restrict__ ei, const float* __restrict__ w) {
    int e = blockIdx.x * blockDim.x + threadIdx.x;
    if (e >= TE) return;
    int src = ei[e];
    int dst = (e < EE) ? ei[e + EE] : ei[e - EE];
    if ((unsigned)src >= (unsigned)NN || (unsigned)dst >= (unsigned)NN) return;
    int pos = atomicAdd(&g_cur[dst], 1);
    float wv = w[e];
    float rn = __ldg(&g_rn[src]);
    g_csr1[pos] = make_int2(src, __float_as_int(wv * rn));
    g_csr2[pos] = make_int2(src, __float_as_int(wv));
}

// ---------------------------------------------------------------------------
// Pull conv — proven R2 structure: one warp per dst row, float2 per lane.
// Coalesced 32-edge batch preload of {src,w}; simple ROLLED shfl-broadcast
// inner loop, one LDG per iteration (R7/R9 evidence: front-batching loads
// regresses via cross-CTA L1tex queue contention). Atomic-free.
// FINAL epilogue reconstructs xn[row] = emb[row]*rn[row] on the fly.
template <bool FINAL>
__global__ void k_gather(const float* __restrict__ xin,
                         const int2* __restrict__ csr,
                         const float* __restrict__ emb,
                         float* __restrict__ xout) {
    int row  = blockIdx.x * 8 + (threadIdx.x >> 5);
    if (row >= NN) return;
    int lane = threadIdx.x & 31;
    int start = __ldg(&g_off[row]);
    int cnt   = __ldg(&g_cnt[row]);
    float2 acc = make_float2(0.f, 0.f);
    for (int b = 0; b < cnt; b += 32) {
        int idx = b + lane;
        int2 pr = (idx < cnt) ? __ldg(&csr[start + idx]) : make_int2(0, 0);
        int m = min(32, cnt - b);
        for (int j = 0; j < m; j++) {
            int   sj = __shfl_sync(0xffffffffu, pr.x, j);
            float wj = __int_as_float(__shfl_sync(0xffffffffu, pr.y, j));
            const float2 v = *(const float2*)(xin + (size_t)sj * DD + lane * 2);
            acc.x += wj * v.x;
            acc.y += wj * v.y;
        }
    }
    float sc = 1.0f / fmaxf((float)cnt, 1.0f);
    acc.x *= sc; acc.y *= sc;
    acc.x = acc.x >= 0.f ? acc.x : 0.01f * acc.x;
    acc.y = acc.y >= 0.f ? acc.y : 0.01f * acc.y;
    size_t o = (size_t)row * DD + lane * 2;
    if (FINAL) {
        float rn = __ldg(&g_rn[row]);
        float2 em = *(const float2*)(emb + o);
        float2 x1 = *(const float2*)(g_x1 + o);
        acc.x += em.x * rn + x1.x;
        acc.y += em.y * rn + x1.y;
    }
    *(float2*)(xout + o) = acc;
}

// ---------------------------------------------------------------------------
extern "C" void kernel_launch(void* const* d_in, const int* in_sizes, int n_in,
                              void* d_out, int out_size) {
    const float* emb = (const float*)d_in[0];   // [NN, DD] float32
    const int*   ei  = (const int*)d_in[1];     // [2, EE] int32
    const float* w   = (const float*)d_in[2];   // [TE, 1] float32
    float* out = (float*)d_out;

    void *p_cnt, *p_x1, *p_csr1, *p_csr2;
    cudaGetSymbolAddress(&p_cnt,  g_cnt);
    cudaGetSymbolAddress(&p_x1,   g_x1);
    cudaGetSymbolAddress(&p_csr1, g_csr1);
    cudaGetSymbolAddress(&p_csr2, g_csr2);

    const int THR = 256;

    // Launch order chosen so k_gather<false> sits at launch index 5
    // (ncu capture is -s 5 -c 1 -> finally profiles the dominant kernel).
    k_rnorm<<<(NN + 15) / 16, THR>>>(emb);                       // 0
    cudaMemsetAsync(p_cnt, 0, (NN + 1) * sizeof(int));           // 1
    k_count<<<(TE + THR - 1) / THR, THR>>>(ei);                  // 2
    k_build_off<<<NBLK, THR>>>();                                // 3
    k_fill<<<(TE + THR - 1) / THR, THR>>>(ei, w);                // 4

    // layer 1: x1 = leaky(gather(emb; w*rn)/deg)   [= gather over xn]
    k_gather<false><<<(NN + 7) / 8, THR>>>(emb, (const int2*)p_csr1,
                                           emb, (float*)p_x1);   // 5
    // layer 2: out = xn + x1 + leaky(gather(x1; w)/deg)
    k_gather<true><<<(NN + 7) / 8, THR>>>((const float*)p_x1, (const int2*)p_csr2,
                                          emb, out);             // 6
}

// round 14
// speedup vs baseline: 1.2273x; 1.0324x over previous
#include <cuda_runtime.h>

#define NN 200000
#define DD 64
#define EE 600000
#define TE 1200000           // 2*EE directed edges after symmetrization
#define NBLK 196             // ceil(NN / 1024) build blocks
#define RNB 12500            // rnorm blocks (16 rows each)
#define CNB 4688             // count blocks (256 edges each)

// Scratch: __device__ globals (no allocation allowed anywhere).
__device__ float g_x1[(size_t)NN * DD];    // layer-1 output
__device__ float g_rn[NN];                 // 1 / max(||emb_row||, eps)
__device__ int   g_cnt[NN + 1];            // in-degree; [NN] = global cursor
__device__ int   g_off[NN];                // CSR bucket start
__device__ int   g_cur[NN];                // fill cursors
__device__ int4  g_csr[TE];                // slot: {src, bits(w*rn[src]), bits(w), 0}

// ---------------------------------------------------------------------------
// Fused pre-pass. Blocks [0, RNB): per-row inverse L2 norm (one half-warp per
// row, float4/lane). Blocks [RNB, RNB+CNB): degree histogram (one thread per
// directed edge; src = ei[e], dst = ei[e^mirror]).
__global__ void k_pre(const float* __restrict__ x, const int* __restrict__ ei) {
    if (blockIdx.x < RNB) {
        int warp = threadIdx.x >> 5;
        int lane = threadIdx.x & 31;
        int h    = lane >> 4;
        int f    = lane & 15;
        int row  = blockIdx.x * 16 + warp * 2 + h;
        if (row >= NN) return;
        const float4 v = *(const float4*)(x + (size_t)row * DD + f * 4);
        float s = v.x * v.x + v.y * v.y + v.z * v.z + v.w * v.w;
        #pragma unroll
        for (int o = 8; o; o >>= 1) s += __shfl_xor_sync(0xffffffffu, s, o);
        if (f == 0) g_rn[row] = 1.0f / fmaxf(sqrtf(s), 1e-12f);
    } else {
        int e = (blockIdx.x - RNB) * blockDim.x + threadIdx.x;
        if (e >= TE) return;
        int dst = (e < EE) ? ei[e + EE] : ei[e - EE];
        if ((unsigned)dst < (unsigned)NN) atomicAdd(&g_cnt[dst], 1);
    }
}

// ---------------------------------------------------------------------------
// Bucket allocation: each block scans 1024 counts, grabs a contiguous range
// from the global cursor (g_cnt[NN]) with ONE atomic, writes off/cur. Bucket
// placement order is nondeterministic but content per bucket is fixed.
__global__ void k_build_off() {
    __shared__ int sh[256];
    __shared__ int base_sh;
    int t = threadIdx.x;
    int b = blockIdx.x * 1024 + t * 4;
    int v0 = (b + 0 < NN) ? g_cnt[b + 0] : 0;
    int v1 = (b + 1 < NN) ? g_cnt[b + 1] : 0;
    int v2 = (b + 2 < NN) ? g_cnt[b + 2] : 0;
    int v3 = (b + 3 < NN) ? g_cnt[b + 3] : 0;
    int s = v0 + v1 + v2 + v3;
    sh[t] = s;
    __syncthreads();
    #pragma unroll
    for (int o = 1; o < 256; o <<= 1) {
        int x = (t >= o) ? sh[t - o] : 0;
        __syncthreads();
        sh[t] += x;
        __syncthreads();
    }
    if (t == 255) base_sh = atomicAdd(&g_cnt[NN], sh[255]);
    __syncthreads();
    int excl = base_sh + sh[t] - s;
    if (b + 0 < NN) { g_off[b + 0] = excl;                g_cur[b + 0] = excl; }
    if (b + 1 < NN) { g_off[b + 1] = excl + v0;           g_cur[b + 1] = excl + v0; }
    if (b + 2 < NN) { g_off[b + 2] = excl + v0 + v1;      g_cur[b + 2] = excl + v0 + v1; }
    if (b + 3 < NN) { g_off[b + 3] = excl + v0 + v1 + v2; g_cur[b + 3] = excl + v0 + v1 + v2; }
}

// ---------------------------------------------------------------------------
// CSR fill: ONE STG.128 per edge carrying both layers' weights:
// {src, bits(w*rn[src]) [layer1], bits(w) [layer2], 0}. Single scattered
// address stream (R13 evidence: two separate STG.64 streams cost 27.7us).
__global__ void k_fill(const int* __restrict__ ei, const float* __restrict__ w) {
    int e = blockIdx.x * blockDim.x + threadIdx.x;
    if (e >= TE) return;
    int src = ei[e];
    int dst = (e < EE) ? ei[e + EE] : ei[e - EE];
    if ((unsigned)src >= (unsigned)NN || (unsigned)dst >= (unsigned)NN) return;
    int pos = atomicAdd(&g_cur[dst], 1);
    float wv = w[e];
    float rn = __ldg(&g_rn[src]);
    g_csr[pos] = make_int4(src, __float_as_int(wv * rn), __float_as_int(wv), 0);
}

// ---------------------------------------------------------------------------
// Pull conv — proven R2 structure: one warp per dst row, float2 per lane.
// Coalesced 32-edge batch preload of the int4 slot; simple ROLLED
// shfl-broadcast inner loop, one LDG per iteration (R7/R9 evidence: load
// front-batching regresses via cross-CTA L1tex queue contention). Weight
// component selected at compile time: .y = w*rn (layer 1), .z = w (layer 2).
// FINAL epilogue reconstructs xn[row] = emb[row]*rn[row] on the fly.
template <bool FINAL>
__global__ void k_gather(const float* __restrict__ xin,
                         const float* __restrict__ emb,
                         float* __restrict__ xout) {
    int row  = blockIdx.x * 8 + (threadIdx.x >> 5);
    if (row >= NN) return;
    int lane = threadIdx.x & 31;
    int start = __ldg(&g_off[row]);
    int cnt   = __ldg(&g_cnt[row]);
    float2 acc = make_float2(0.f, 0.f);
    for (int b = 0; b < cnt; b += 32) {
        int idx = b + lane;
        int src_r = 0, wbits_r = 0;
        if (idx < cnt) {
            int4 pr = __ldg(&g_csr[start + idx]);
            src_r   = pr.x;
            wbits_r = FINAL ? pr.z : pr.y;
        }
        int m = min(32, cnt - b);
        for (int j = 0; j < m; j++) {
            int   sj = __shfl_sync(0xffffffffu, src_r, j);
            float wj = __int_as_float(__shfl_sync(0xffffffffu, wbits_r, j));
            const float2 v = *(const float2*)(xin + (size_t)sj * DD + lane * 2);
            acc.x += wj * v.x;
            acc.y += wj * v.y;
        }
    }
    float sc = 1.0f / fmaxf((float)cnt, 1.0f);
    acc.x *= sc; acc.y *= sc;
    acc.x = acc.x >= 0.f ? acc.x : 0.01f * acc.x;
    acc.y = acc.y >= 0.f ? acc.y : 0.01f * acc.y;
    size_t o = (size_t)row * DD + lane * 2;
    if (FINAL) {
        float rn = __ldg(&g_rn[row]);
        float2 em = *(const float2*)(emb + o);
        float2 x1 = *(const float2*)(g_x1 + o);
        acc.x += em.x * rn + x1.x;
        acc.y += em.y * rn + x1.y;
    }
    *(float2*)(xout + o) = acc;
}

// ---------------------------------------------------------------------------
extern "C" void kernel_launch(void* const* d_in, const int* in_sizes, int n_in,
                              void* d_out, int out_size) {
    const float* emb = (const float*)d_in[0];   // [NN, DD] float32
    const int*   ei  = (const int*)d_in[1];     // [2, EE] int32
    const float* w   = (const float*)d_in[2];   // [TE, 1] float32
    float* out = (float*)d_out;

    void *p_cnt, *p_x1;
    cudaGetSymbolAddress(&p_cnt, g_cnt);
    cudaGetSymbolAddress(&p_x1,  g_x1);

    const int THR = 256;

    // CSR build: (rnorm + degrees) -> bucket alloc -> fill
    cudaMemsetAsync(p_cnt, 0, (NN + 1) * sizeof(int));
    k_pre<<<RNB + CNB, THR>>>(emb, ei);
    k_build_off<<<NBLK, THR>>>();
    k_fill<<<(TE + THR - 1) / THR, THR>>>(ei, w);

    // layer 1: x1 = leaky(gather(emb; w*rn)/deg)   [= gather over xn]
    k_gather<false><<<(NN + 7) / 8, THR>>>(emb, emb, (float*)p_x1);
    // layer 2: out = xn + x1 + leaky(gather(x1; w)/deg)
    k_gather<true><<<(NN + 7) / 8, THR>>>((const float*)p_x1, emb, out);
}

// round 15
// speedup vs baseline: 1.2671x; 1.0324x over previous
#include <cuda_runtime.h>

#define NN 200000
#define DD 64
#define EE 600000
#define TE 1200000           // 2*EE directed edges after symmetrization
#define NBLK 196             // ceil(NN / 1024) build blocks
#define RNB 12500            // rnorm blocks (16 rows each)
#define CNB 4688             // count blocks (256 edges each)

// Scratch: __device__ globals (no allocation allowed anywhere).
__device__ float g_x1[(size_t)NN * DD];    // layer-1 output
__device__ float g_rn[NN];                 // 1 / max(||emb_row||, eps)
__device__ int   g_cnt[NN + 1];            // in-degree; [NN] = global cursor
__device__ int   g_off[NN];                // CSR bucket start
__device__ int   g_cur[NN];                // fill cursors
__device__ int4  g_csr[TE];                // slot: {src, bits(w*rn[src]), bits(w), 0}

// ---------------------------------------------------------------------------
// Fused pre-pass. Blocks [0, RNB): per-row inverse L2 norm (one half-warp per
// row, float4/lane). Blocks [RNB, RNB+CNB): degree histogram (one thread per
// directed edge; src = ei[e], dst = ei[e^mirror]).
__global__ void k_pre(const float* __restrict__ x, const int* __restrict__ ei) {
    if (blockIdx.x < RNB) {
        int warp = threadIdx.x >> 5;
        int lane = threadIdx.x & 31;
        int h    = lane >> 4;
        int f    = lane & 15;
        int row  = blockIdx.x * 16 + warp * 2 + h;
        if (row >= NN) return;
        const float4 v = *(const float4*)(x + (size_t)row * DD + f * 4);
        float s = v.x * v.x + v.y * v.y + v.z * v.z + v.w * v.w;
        #pragma unroll
        for (int o = 8; o; o >>= 1) s += __shfl_xor_sync(0xffffffffu, s, o);
        if (f == 0) g_rn[row] = 1.0f / fmaxf(sqrtf(s), 1e-12f);
    } else {
        int e = (blockIdx.x - RNB) * blockDim.x + threadIdx.x;
        if (e >= TE) return;
        int dst = (e < EE) ? ei[e + EE] : ei[e - EE];
        if ((unsigned)dst < (unsigned)NN) atomicAdd(&g_cnt[dst], 1);
    }
}

// ---------------------------------------------------------------------------
// Bucket allocation: each block scans 1024 counts, grabs a contiguous range
// from the global cursor (g_cnt[NN]) with ONE atomic, writes off/cur. Bucket
// placement order is nondeterministic but content per bucket is fixed.
__global__ void k_build_off() {
    __shared__ int sh[256];
    __shared__ int base_sh;
    int t = threadIdx.x;
    int b = blockIdx.x * 1024 + t * 4;
    int v0 = (b + 0 < NN) ? g_cnt[b + 0] : 0;
    int v1 = (b + 1 < NN) ? g_cnt[b + 1] : 0;
    int v2 = (b + 2 < NN) ? g_cnt[b + 2] : 0;
    int v3 = (b + 3 < NN) ? g_cnt[b + 3] : 0;
    int s = v0 + v1 + v2 + v3;
    sh[t] = s;
    __syncthreads();
    #pragma unroll
    for (int o = 1; o < 256; o <<= 1) {
        int x = (t >= o) ? sh[t - o] : 0;
        __syncthreads();
        sh[t] += x;
        __syncthreads();
    }
    if (t == 255) base_sh = atomicAdd(&g_cnt[NN], sh[255]);
    __syncthreads();
    int excl = base_sh + sh[t] - s;
    if (b + 0 < NN) { g_off[b + 0] = excl;                g_cur[b + 0] = excl; }
    if (b + 1 < NN) { g_off[b + 1] = excl + v0;           g_cur[b + 1] = excl + v0; }
    if (b + 2 < NN) { g_off[b + 2] = excl + v0 + v1;      g_cur[b + 2] = excl + v0 + v1; }
    if (b + 3 < NN) { g_off[b + 3] = excl + v0 + v1 + v2; g_cur[b + 3] = excl + v0 + v1 + v2; }
}

// ---------------------------------------------------------------------------
// CSR fill: ONE STG.128 per edge carrying both layers' weights:
// {src, bits(w*rn[src]) [layer1], bits(w) [layer2], 0}.
__global__ void k_fill(const int* __restrict__ ei, const float* __restrict__ w) {
    int e = blockIdx.x * blockDim.x + threadIdx.x;
    if (e >= TE) return;
    int src = ei[e];
    int dst = (e < EE) ? ei[e + EE] : ei[e - EE];
    if ((unsigned)src >= (unsigned)NN || (unsigned)dst >= (unsigned)NN) return;
    int pos = atomicAdd(&g_cur[dst], 1);
    float wv = w[e];
    float rn = __ldg(&g_rn[src]);
    g_csr[pos] = make_int4(src, __float_as_int(wv * rn), __float_as_int(wv), 0);
}

// ---------------------------------------------------------------------------
// Pull conv — TWO rows per warp: half-warp per row, float4 per lane (16 lanes
// x 16B = full 256B row). Each inner iteration: one shfl pair with per-half
// source lanes + ONE warp-wide LDG.128 servicing BOTH rows (2 edges per load
// slot, MLP_p1 stays 1 — avoids the R7/R9 front-batch regression). Preload is
// 16 slots per half-warp; iterations run to max(cntA,cntB), padded edges have
// wj=0. Weight component picked at compile time: .y = w*rn (L1), .z = w (L2).
// FINAL epilogue reconstructs xn[row] = emb[row]*rn[row] on the fly.
template <bool FINAL>
__global__ void k_gather(const float* __restrict__ xin,
                         const float* __restrict__ emb,
                         float* __restrict__ xout) {
    int wid  = blockIdx.x * 8 + (threadIdx.x >> 5);   // warp id = row pair
    int lane = threadIdx.x & 31;
    int h    = lane >> 4;          // row within pair
    int f    = lane & 15;          // feature group (float4 at f*4)
    int row  = wid * 2 + h;        // NN = 2*8*12500 exactly -> always valid
    int start = __ldg(&g_off[row]);
    int cnt   = __ldg(&g_cnt[row]);
    int cmax  = max(cnt, __shfl_xor_sync(0xffffffffu, cnt, 16));
    int hbase = h << 4;
    float4 acc = make_float4(0.f, 0.f, 0.f, 0.f);
    for (int b = 0; b < cmax; b += 16) {
        int idx = b + f;           // each half-warp preloads 16 of its slots
        int src_r = 0, wbits_r = 0;
        if (idx < cnt) {
            int4 pr = __ldg(&g_csr[start + idx]);
            src_r   = pr.x;
            wbits_r = FINAL ? pr.z : pr.y;
        }
        int m = min(16, cmax - b);
        for (int j = 0; j < m; j++) {
            int   sl = hbase + j;  // broadcast from own half's slot j
            int   sj = __shfl_sync(0xffffffffu, src_r, sl);
            float wj = __int_as_float(__shfl_sync(0xffffffffu, wbits_r, sl));
            const float4 v = *(const float4*)(xin + (size_t)sj * DD + f * 4);
            acc.x += wj * v.x;
            acc.y += wj * v.y;
            acc.z += wj * v.z;
            acc.w += wj * v.w;
        }
    }
    float sc = 1.0f / fmaxf((float)cnt, 1.0f);
    acc.x *= sc; acc.y *= sc; acc.z *= sc; acc.w *= sc;
    acc.x = acc.x >= 0.f ? acc.x : 0.01f * acc.x;
    acc.y = acc.y >= 0.f ? acc.y : 0.01f * acc.y;
    acc.z = acc.z >= 0.f ? acc.z : 0.01f * acc.z;
    acc.w = acc.w >= 0.f ? acc.w : 0.01f * acc.w;
    size_t o = (size_t)row * DD + f * 4;
    if (FINAL) {
        float rn = __ldg(&g_rn[row]);
        float4 em = *(const float4*)(emb + o);
        float4 x1 = *(const float4*)(g_x1 + o);
        acc.x += em.x * rn + x1.x;
        acc.y += em.y * rn + x1.y;
        acc.z += em.z * rn + x1.z;
        acc.w += em.w * rn + x1.w;
    }
    *(float4*)(xout + o) = acc;
}

// ---------------------------------------------------------------------------
extern "C" void kernel_launch(void* const* d_in, const int* in_sizes, int n_in,
                              void* d_out, int out_size) {
    const float* emb = (const float*)d_in[0];   // [NN, DD] float32
    const int*   ei  = (const int*)d_in[1];     // [2, EE] int32
    const float* w   = (const float*)d_in[2];   // [TE, 1] float32
    float* out = (float*)d_out;

    void *p_cnt, *p_x1;
    cudaGetSymbolAddress(&p_cnt, g_cnt);
    cudaGetSymbolAddress(&p_x1,  g_x1);

    const int THR = 256;
    const int GGRID = NN / 16;   // 2 rows/warp * 8 warps/block = 16 rows/block

    // CSR build: (rnorm + degrees) -> bucket alloc -> fill
    cudaMemsetAsync(p_cnt, 0, (NN + 1) * sizeof(int));
    k_pre<<<RNB + CNB, THR>>>(emb, ei);
    k_build_off<<<NBLK, THR>>>();
    k_fill<<<(TE + THR - 1) / THR, THR>>>(ei, w);

    // layer 1: x1 = leaky(gather(emb; w*rn)/deg)   [= gather over xn]
    k_gather<false><<<GGRID, THR>>>(emb, emb, (float*)p_x1);
    // layer 2: out = xn + x1 + leaky(gather(x1; w)/deg)
    k_gather<true><<<GGRID, THR>>>((const float*)p_x1, emb, out);
}

// round 17
// speedup vs baseline: 1.4974x; 1.1818x over previous
#include <cuda_runtime.h>

#define NN 200000
#define DD 64
#define EE 600000
#define TE 1200000           // 2*EE directed edges after symmetrization
#define NBLK 196             // ceil(NN / 1024) build blocks
#define RNB 12500            // rnorm blocks (16 rows each)
#define CNB 4688             // count blocks (256 edges each)

// Scratch: __device__ globals (no allocation allowed anywhere).
__device__ float g_x1[(size_t)NN * DD];    // layer-1 output
__device__ float g_rn[NN];                 // 1 / max(||emb_row||, eps)
__device__ int   g_cnt[NN + 1];            // in-degree; [NN] = global cursor
__device__ int   g_off[NN];                // CSR bucket start
__device__ int   g_cur[NN];                // fill cursors
__device__ int4  g_csr[TE];                // slot: {src, bits(w*rn), src, bits(w)}

// ---------------------------------------------------------------------------
// Fused pre-pass. Blocks [0, RNB): per-row inverse L2 norm (one half-warp per
// row, float4/lane). Blocks [RNB, RNB+CNB): degree histogram (one thread per
// directed edge; src = ei[e], dst = ei[e^mirror]).
__global__ void k_pre(const float* __restrict__ x, const int* __restrict__ ei) {
    if (blockIdx.x < RNB) {
        int warp = threadIdx.x >> 5;
        int lane = threadIdx.x & 31;
        int h    = lane >> 4;
        int f    = lane & 15;
        int row  = blockIdx.x * 16 + warp * 2 + h;
        if (row >= NN) return;
        const float4 v = *(const float4*)(x + (size_t)row * DD + f * 4);
        float s = v.x * v.x + v.y * v.y + v.z * v.z + v.w * v.w;
        #pragma unroll
        for (int o = 8; o; o >>= 1) s += __shfl_xor_sync(0xffffffffu, s, o);
        if (f == 0) g_rn[row] = 1.0f / fmaxf(sqrtf(s), 1e-12f);
    } else {
        int e = (blockIdx.x - RNB) * blockDim.x + threadIdx.x;
        if (e >= TE) return;
        int dst = (e < EE) ? ei[e + EE] : ei[e - EE];
        if ((unsigned)dst < (unsigned)NN) atomicAdd(&g_cnt[dst], 1);
    }
}

// ---------------------------------------------------------------------------
// Bucket allocation: each block scans 1024 counts, grabs a contiguous range
// from the global cursor (g_cnt[NN]) with ONE atomic, writes off/cur. Bucket
// placement order is nondeterministic but content per bucket is fixed.
__global__ void k_build_off() {
    __shared__ int sh[256];
    __shared__ int base_sh;
    int t = threadIdx.x;
    int b = blockIdx.x * 1024 + t * 4;
    int v0 = (b + 0 < NN) ? g_cnt[b + 0] : 0;
    int v1 = (b + 1 < NN) ? g_cnt[b + 1] : 0;
    int v2 = (b + 2 < NN) ? g_cnt[b + 2] : 0;
    int v3 = (b + 3 < NN) ? g_cnt[b + 3] : 0;
    int s = v0 + v1 + v2 + v3;
    sh[t] = s;
    __syncthreads();
    #pragma unroll
    for (int o = 1; o < 256; o <<= 1) {
        int x = (t >= o) ? sh[t - o] : 0;
        __syncthreads();
        sh[t] += x;
        __syncthreads();
    }
    if (t == 255) base_sh = atomicAdd(&g_cnt[NN], sh[255]);
    __syncthreads();
    int excl = base_sh + sh[t] - s;
    if (b + 0 < NN) { g_off[b + 0] = excl;                g_cur[b + 0] = excl; }
    if (b + 1 < NN) { g_off[b + 1] = excl + v0;           g_cur[b + 1] = excl + v0; }
    if (b + 2 < NN) { g_off[b + 2] = excl + v0 + v1;      g_cur[b + 2] = excl + v0 + v1; }
    if (b + 3 < NN) { g_off[b + 3] = excl + v0 + v1 + v2; g_cur[b + 3] = excl + v0 + v1 + v2; }
}

// ---------------------------------------------------------------------------
// CSR fill: ONE STG.128 per edge; slot layout {src, bits(w*rn), src, bits(w)}
// duplicates src so each layer's gather reads a contiguous int2 (LDG.64).
__global__ void k_fill(const int* __restrict__ ei, const float* __restrict__ w) {
    int e = blockIdx.x * blockDim.x + threadIdx.x;
    if (e >= TE) return;
    int src = ei[e];
    int dst = (e < EE) ? ei[e + EE] : ei[e - EE];
    if ((unsigned)src >= (unsigned)NN || (unsigned)dst >= (unsigned)NN) return;
    int pos = atomicAdd(&g_cur[dst], 1);
    float wv = w[e];
    float rn = __ldg(&g_rn[src]);
    g_csr[pos] = make_int4(src, __float_as_int(wv * rn), src, __float_as_int(wv));
}

// ---------------------------------------------------------------------------
// Pull conv — TWO rows per warp (R15-validated): half-warp per row, float4
// per lane. One shfl pair + ONE warp-wide LDG.128 per iteration services both
// rows. __launch_bounds__(256,8) caps regs at 32 -> 64 resident warps/SM
// (R15 profile: regs=41 collapsed occ to 49%). CSR preload is an int2
// (layer-selected half of the slot). Padded edges carry wj=0.
// FINAL epilogue reconstructs xn[row] = emb[row]*rn[row] on the fly.
template <bool FINAL>
__global__ void __launch_bounds__(256, 8)
k_gather(const float* __restrict__ xin,
         const float* __restrict__ emb,
         float* __restrict__ xout) {
    int wid  = blockIdx.x * 8 + (threadIdx.x >> 5);   // warp id = row pair
    int lane = threadIdx.x & 31;
    int h    = lane >> 4;          // row within pair
    int f    = lane & 15;          // feature group (float4 at f*4)
    int row  = wid * 2 + h;        // NN = 2*8*12500 exactly -> always valid
    int start = __ldg(&g_off[row]);
    int cnt   = __ldg(&g_cnt[row]);
    int cmax  = max(cnt, __shfl_xor_sync(0xffffffffu, cnt, 16));
    int hbase = h << 4;
    const int2* csr2 = ((const int2*)g_csr) + (FINAL ? 1 : 0);
    float4 acc = make_float4(0.f, 0.f, 0.f, 0.f);
    for (int b = 0; b < cmax; b += 16) {
        int idx = b + f;           // each half-warp preloads 16 of its slots
        int src_r = 0, wbits_r = 0;
        if (idx < cnt) {
            int2 pr = __ldg(&csr2[2 * (start + idx)]);
            src_r   = pr.x;
            wbits_r = pr.y;
        }
        int m = min(16, cmax - b);
        for (int j = 0; j < m; j++) {
            int   sl = hbase + j;  // broadcast from own half's slot j
            int   sj = __shfl_sync(0xffffffffu, src_r, sl);
            float wj = __int_as_float(__shfl_sync(0xffffffffu, wbits_r, sl));
            const float4 v = *(const float4*)(xin + (size_t)sj * DD + f * 4);
            acc.x += wj * v.x;
            acc.y += wj * v.y;
            acc.z += wj * v.z;
            acc.w += wj * v.w;
        }
    }
    float sc = 1.0f / fmaxf((float)cnt, 1.0f);
    acc.x *= sc; acc.y *= sc; acc.z *= sc; acc.w *= sc;
    acc.x = acc.x >= 0.f ? acc.x : 0.01f * acc.x;
    acc.y = acc.y >= 0.f ? acc.y : 0.01f * acc.y;
    acc.z = acc.z >= 0.f ? acc.z : 0.01f * acc.z;
    acc.w = acc.w >= 0.f ? acc.w : 0.01f * acc.w;
    size_t o = (size_t)row * DD + f * 4;
    if (FINAL) {
        float rn = __ldg(&g_rn[row]);
        float4 em = *(const float4*)(emb + o);
        float4 x1 = *(const float4*)(g_x1 + o);
        acc.x += em.x * rn + x1.x;
        acc.y += em.y * rn + x1.y;
        acc.z += em.z * rn + x1.z;
        acc.w += em.w * rn + x1.w;
    }
    *(float4*)(xout + o) = acc;
}

// ---------------------------------------------------------------------------
extern "C" void kernel_launch(void* const* d_in, const int* in_sizes, int n_in,
                              void* d_out, int out_size) {
    const float* emb = (const float*)d_in[0];   // [NN, DD] float32
    const int*   ei  = (const int*)d_in[1];     // [2, EE] int32
    const float* w   = (const float*)d_in[2];   // [TE, 1] float32
    float* out = (float*)d_out;

    void *p_cnt, *p_x1;
    cudaGetSymbolAddress(&p_cnt, g_cnt);
    cudaGetSymbolAddress(&p_x1,  g_x1);

    const int THR = 256;
    const int GGRID = NN / 16;   // 2 rows/warp * 8 warps/block = 16 rows/block

    // CSR build: (rnorm + degrees) -> bucket alloc -> fill
    cudaMemsetAsync(p_cnt, 0, (NN + 1) * sizeof(int));
    k_pre<<<RNB + CNB, THR>>>(emb, ei);
    k_build_off<<<NBLK, THR>>>();
    k_fill<<<(TE + THR - 1) / THR, THR>>>(ei, w);

    // layer 1: x1 = leaky(gather(emb; w*rn)/deg)   [= gather over xn]
    k_gather<false><<<GGRID, THR>>>(emb, emb, (float*)p_x1);
    // layer 2: out = xn + x1 + leaky(gather(x1; w)/deg)
    k_gather<true><<<GGRID, THR>>>((const float*)p_x1, emb, out);
}